// round 17
// baseline (speedup 1.0000x reference)
#include <cuda_runtime.h>
#include <cuda_fp16.h>
#include <math.h>

// RenderNet volume rendering — round 17.
// K1: 2048x128, FOUR threads per ray (quarter-scan): lane-quarter q computes
//     z[16q:16q+16) with local trans; exclusive prefix product across the 4
//     lanes via guarded Hillis-Steele shfl scan rescales each quarter
//     (algebraically identical cumprod incl. +1e-10 terms). Serial MUFU chain
//     64 -> 16 steps. __expf; fp16 weights packed half2 across ray pairs.
// K2: FROZEN R15/R16 body (740x256, 5 CTA/SM, 6.5TB/s, at traffic floor):
//     warp = 4 channels x 8 ray-quads; fp16 weights one 64B line/warp/z;
//     feat LDG.128 .cs; fast sigmoid; __stcs outputs.
// out: [0]=loss, [1..1+CN)=rgb_e, [1+CN..1+2CN)=feat_e, [..+N)=acc_e
// (out+1 only 4B-aligned -> scalar output stores).

#define RN_C 32
#define RN_Z 64
#define RN_N 65536
#define RAW_NOISE_STD 0.1f
#define FAR_DIST 1e10f

#define K1_THREADS 128
#define K1_GRID ((RN_N * 4) / K1_THREADS)            // 2048

#define K2_GRID 740            // 5 CTAs/SM * 148 SMs, single wave
#define K2_THREADS 256
#define K2_NWARPS (K2_GRID * K2_THREADS / 32)       // 5920
#define K2_WARPJOBS ((RN_C / 4) * (RN_N / 4 / 8))   // 16384

__device__ __half g_wbuf[RN_Z * RN_N];   // weights [z][n], fp16, 8MB

// ---------------- K1: weights, quarter-scan 4 threads/ray ----------------
__global__ void __launch_bounds__(K1_THREADS)
rn_weights(const float* __restrict__ occ,
           const float* __restrict__ z_dist,
           const float* __restrict__ noise,
           float* __restrict__ out)
{
    __shared__ float s_dist[RN_Z];
    const int tid = threadIdx.x;
    if (tid < RN_Z)
        s_dist[tid] = (tid < RN_Z - 1) ? (z_dist[tid + 1] - z_dist[tid]) : FAR_DIST;
    __syncthreads();

    const int g     = blockIdx.x * K1_THREADS + tid;
    const int n     = g >> 2;          // ray
    const int q     = g & 3;           // quarter: z[16q : 16q+16)
    const int zbase = q << 4;
    const unsigned mask = 0xffffffffu;

    // noise: 4 float4 = 64B contiguous (this thread's quarter of row n)
    const float4* np4 = (const float4*)(noise + (size_t)n * RN_Z + zbase);
    float4 nq[4];
#pragma unroll
    for (int j = 0; j < 4; ++j) nq[j] = __ldcs(np4 + j);

    // occ: 16 independent scalars; same-quarter lanes are consecutive rays
    float ov[16];
#pragma unroll
    for (int j = 0; j < 16; ++j)
        ov[j] = __ldcs(occ + (size_t)(zbase + j) * RN_N + n);

    float nv[16];
#pragma unroll
    for (int j = 0; j < 4; ++j) {
        nv[4 * j + 0] = nq[j].x; nv[4 * j + 1] = nq[j].y;
        nv[4 * j + 2] = nq[j].z; nv[4 * j + 3] = nq[j].w;
    }

    // local 16-step recurrence (trans starts at 1 in every quarter)
    float trans = 1.0f, wsum = 0.0f;
    float w[16];
#pragma unroll
    for (int j = 0; j < 16; ++j) {
        float raw   = fmaxf(fmaf(nv[j], RAW_NOISE_STD, ov[j]), 0.0f);
        float alpha = 1.0f - __expf(-raw * s_dist[zbase + j]);
        w[j] = alpha * trans;
        trans *= (1.0f - alpha + 1e-10f);
        wsum += w[j];
    }

    // 4-lane product scan (guards keep it inside each ray's lane group):
    float inc = trans;
    float t1 = __shfl_up_sync(mask, inc, 1);
    if (q >= 1) inc *= t1;
    float t2 = __shfl_up_sync(mask, inc, 2);
    if (q >= 2) inc *= t2;
    float exc = __shfl_up_sync(mask, inc, 1);   // exclusive prefix product
    if (q == 0) exc = 1.0f;

    // acc_map: sum exc_q * wsum_q across the 4 quarters (xor stays in-group)
    float s = exc * wsum;
    s += __shfl_xor_sync(mask, s, 1);
    s += __shfl_xor_sync(mask, s, 2);
    if (q == 0) {
        float* amp = out + 1 + 2 * (size_t)RN_C * RN_N;
        amp[n] = fminf(fmaxf(s, 0.0f), 1.0f);
    }

    // scale + pack half2 across ray pair: lane l pairs with l+4 (ray n+1,
    // same quarter); storing lanes have (tid&4)==0 -> n even -> 4B aligned.
#pragma unroll
    for (int j = 0; j < 16; ++j) {
        float ws  = w[j] * exc;
        float ws2 = __shfl_down_sync(mask, ws, 4);
        if ((tid & 4) == 0)
            *(__half2*)&g_wbuf[(size_t)(zbase + j) * RN_N + n] =
                __floats2half2_rn(ws, ws2);
    }

    if (g == 0) out[0] = 0.0f;
}

// ---------------- K2: composite (frozen) ----------------
__global__ void __launch_bounds__(K2_THREADS, 5)
rn_composite(const float* __restrict__ feat,
             float* __restrict__ out)
{
    const int wid0 = (blockIdx.x * K2_THREADS + threadIdx.x) >> 5;
    const int lane = threadIdx.x & 31;
    const int c2   = lane >> 3;     // 0..3 channel within group
    const int q8   = lane & 7;      // 0..7 quad within group

    float* rgb = out + 1;
    float* fe  = out + 1 + (size_t)RN_C * RN_N;
    const size_t ZN = (size_t)RN_Z * (size_t)RN_N;

    for (int wj = wid0; wj < K2_WARPJOBS; wj += K2_NWARPS) {
        const int cg = wj >> 11;               // 0..7 channel group
        const int qg = wj & 2047;              // 0..2047 quad group
        const int c  = cg * 4 + c2;            // channel 0..31
        const int n0 = (qg * 8 + q8) * 4;      // ray start

        const float*  fp = feat + (size_t)c * ZN + n0;
        const __half* wp = g_wbuf + n0;

        float4 a = {0.f, 0.f, 0.f, 0.f};
#pragma unroll 4
        for (int z = 0; z < RN_Z; ++z) {
            uint2 wraw = __ldg((const uint2*)(wp + (size_t)z * RN_N));
            const __half2* wh = (const __half2*)&wraw;
            float2 w01 = __half22float2(wh[0]);
            float2 w23 = __half22float2(wh[1]);
            float4 v = __ldcs((const float4*)(fp + (size_t)z * RN_N));
            a.x = fmaf(w01.x, v.x, a.x);
            a.y = fmaf(w01.y, v.y, a.y);
            a.z = fmaf(w23.x, v.z, a.z);
            a.w = fmaf(w23.y, v.w, a.w);
        }

        const size_t o0 = (size_t)c * RN_N + n0;
        float av[4] = {a.x, a.y, a.z, a.w};
#pragma unroll
        for (int j = 0; j < 4; ++j) {
            __stcs(&fe[o0 + j], av[j]);
            __stcs(&rgb[o0 + j],
                   __fdividef(1.0f, 1.0f + __expf(-av[j])) - 0.5f);
        }
    }
}

// ---------------- generic fallback (any Z/N) ----------------
__global__ void __launch_bounds__(256)
rendernet_generic(const float* __restrict__ feat,
                  const float* __restrict__ occ,
                  const float* __restrict__ z_dist,
                  const float* __restrict__ noise,
                  float* __restrict__ out,
                  int Z, int N)
{
    extern __shared__ float s_d[];
    int tid = threadIdx.x;
    if (tid < Z)
        s_d[tid] = (tid < Z - 1) ? (z_dist[tid + 1] - z_dist[tid]) : FAR_DIST;
    __syncthreads();

    int n = blockIdx.x * blockDim.x + tid;
    if (n >= N) return;

    float acc[RN_C];
#pragma unroll
    for (int c = 0; c < RN_C; ++c) acc[c] = 0.0f;

    const float* occp   = occ + n;
    const float* noisep = noise + (size_t)n * Z;
    const float* featp  = feat + n;
    const size_t ZN = (size_t)Z * (size_t)N;

    float trans = 1.0f, wsum = 0.0f;
    for (int z = 0; z < Z; ++z) {
        float raw = fmaxf(fmaf(noisep[z], RAW_NOISE_STD, occp[(size_t)z * N]), 0.0f);
        float alpha = 1.0f - expf(-raw * s_d[z]);
        float w = alpha * trans;
        trans *= (1.0f - alpha + 1e-10f);
        wsum += w;
        const float* fz = featp + (size_t)z * N;
#pragma unroll
        for (int c = 0; c < RN_C; ++c)
            acc[c] = fmaf(w, fz[(size_t)c * ZN], acc[c]);
    }
    float* rgb = out + 1;
    float* fe  = out + 1 + (size_t)RN_C * N;
    float* am  = out + 1 + 2 * (size_t)RN_C * N;
#pragma unroll
    for (int c = 0; c < RN_C; ++c) {
        float f = acc[c];
        fe[(size_t)c * N + n]  = f;
        rgb[(size_t)c * N + n] = 1.0f / (1.0f + expf(-f)) - 0.5f;
    }
    am[n] = fminf(fmaxf(wsum, 0.0f), 1.0f);
    if (n == 0) out[0] = 0.0f;
}

extern "C" void kernel_launch(void* const* d_in, const int* in_sizes, int n_in,
                              void* d_out, int out_size)
{
    const float* feat   = (const float*)d_in[0];
    const float* occ    = (const float*)d_in[1];
    const float* z_dist = (const float*)d_in[2];
    const float* noise  = (const float*)d_in[3];
    float* out = (float*)d_out;

    int Z = in_sizes[2];
    int N = in_sizes[1] / Z;

    if (Z == RN_Z && N == RN_N) {
        rn_weights<<<K1_GRID, K1_THREADS>>>(occ, z_dist, noise, out);
        rn_composite<<<K2_GRID, K2_THREADS>>>(feat, out);
    } else {
        int block = 256;
        int grid = (N + block - 1) / block;
        rendernet_generic<<<grid, block, Z * sizeof(float)>>>(feat, occ, z_dist, noise, out, Z, N);
    }
}